// round 12
// baseline (speedup 1.0000x reference)
#include <cuda_runtime.h>
#include <cstdint>

// BidirectionalSoftmax: B=8, L1=L2=2048, TAU=0.5, EPS=1e-8
// No-max softmax: e = exp2(sim*(1/TAU)*log2 e); out = sqrt(EPS + e*e*irs*ics)
//
//   k_colstats : finer slabs for tail balance: 2048 CTAs (2 col-groups x
//                128 slabs x 8 b), slab = 16 contiguous rows, unroll-8.
//   k_merge    : fold 128 slab partials -> 1/col_sum, .cs reads so the 8MB
//                partial stream doesn't evict the L2-resident sim region.
//   k_out      : proven block-per-row + .cs streaming hints (UNCHANGED).

#define NB    8
#define NL    2048
#define NSLAB 128
#define RPS   16                      /* rows per slab */
#define SCALEV 2.8853900817779268f    /* (1/0.5) * log2(e) */
#define EPSV  1e-8f

__device__ float g_cps[NB * NSLAB * NL];  // partial col sums of exp2(y)
__device__ float g_ics[NB * NL];          // 1/col_sum

__device__ __forceinline__ float ex2f(float x) {
    float r; asm("ex2.approx.f32 %0, %1;" : "=f"(r) : "f"(x)); return r;
}
__device__ __forceinline__ float sqrtap(float x) {
    float r; asm("sqrt.approx.f32 %0, %1;" : "=f"(r) : "f"(x)); return r;
}
__device__ __forceinline__ float4 ldcs4(const float4* p) {
    float4 v;
    asm volatile("ld.global.cs.v4.f32 {%0,%1,%2,%3}, [%4];"
                 : "=f"(v.x), "=f"(v.y), "=f"(v.z), "=f"(v.w) : "l"(p));
    return v;
}
__device__ __forceinline__ float ldcs1(const float* p) {
    float v;
    asm volatile("ld.global.cs.f32 %0, [%1];" : "=f"(v) : "l"(p));
    return v;
}
__device__ __forceinline__ void stcs4(float4* p, float4 v) {
    asm volatile("st.global.cs.v4.f32 [%0], {%1,%2,%3,%4};"
                 :: "l"(p), "f"(v.x), "f"(v.y), "f"(v.z), "f"(v.w) : "memory");
}

// ---------------------------------------------------------------------------
// Pass 1: column sum partials. grid=(2, 128, 8) = 2048 CTAs, block=256.
// Thread owns 4 consecutive columns; slab = 16 contiguous rows; unroll 8.
// ---------------------------------------------------------------------------
__global__ void __launch_bounds__(256) k_colstats(const float* __restrict__ sim,
                                                  const int*   __restrict__ len) {
    int b = blockIdx.z, slab = blockIdx.y, grp = blockIdx.x;
    int t = threadIdx.x;
    int col = grp * 1024 + t * 4;
    int len1 = __ldg(&len[2 * b]);
    int len2 = __ldg(&len[2 * b + 1]);
    int r0 = slab * RPS;
    int rend = min(r0 + RPS, len1);

    float s0 = 0.f, s1 = 0.f, s2 = 0.f, s3 = 0.f;

    if (col < len2 && r0 < rend) {
        int nv = len2 - col;            // >= 1
        bool k1 = nv > 1, k2 = nv > 2, k3 = nv > 3;
        const float4* p = reinterpret_cast<const float4*>(sim)
                        + ((size_t)b << 20) + ((size_t)r0 << 9) + (col >> 2);
        int n = rend - r0;

#define PROC(v)                                        \
        do {                                           \
            s0 += ex2f((v).x * SCALEV);                \
            s1 += k1 ? ex2f((v).y * SCALEV) : 0.f;     \
            s2 += k2 ? ex2f((v).z * SCALEV) : 0.f;     \
            s3 += k3 ? ex2f((v).w * SCALEV) : 0.f;     \
        } while (0)

        int r = 0;
        for (; r + 8 <= n; r += 8) {
            float4 v[8];
#pragma unroll
            for (int u = 0; u < 8; u++) v[u] = p[u * 512];
            p += 8 * 512;
#pragma unroll
            for (int u = 0; u < 8; u++) PROC(v[u]);
        }
        for (; r < n; r++) { float4 v = p[0]; p += 512; PROC(v); }
#undef PROC
    }

    size_t idx = ((size_t)(b * NSLAB + slab) << 11) + col;
    *reinterpret_cast<float4*>(&g_cps[idx]) = make_float4(s0, s1, s2, s3);
}

// ---------------------------------------------------------------------------
// Pass 1b: fold 128 slab partials per (batch, column) -> 1/col_sum.
// .cs reads: don't let the partial stream evict L2-resident sim data.
// ---------------------------------------------------------------------------
__global__ void __launch_bounds__(256) k_merge() {
    int idx = blockIdx.x * 256 + threadIdx.x;     // b*NL + j
    int b = idx >> 11, j = idx & (NL - 1);

    float acc = 0.f;
#pragma unroll 8
    for (int s = 0; s < NSLAB; s++)
        acc += ldcs1(&g_cps[((size_t)(b * NSLAB + s) << 11) + j]);
    g_ics[idx] = acc > 0.f ? (1.0f / acc) : 0.f;
}

// ---------------------------------------------------------------------------
// Pass 2: block-per-row + streaming cache hints. [PROVEN ~35us, UNCHANGED]
// ---------------------------------------------------------------------------
__global__ void __launch_bounds__(256) k_out(const float* __restrict__ sim,
                                             const int*   __restrict__ len,
                                             float*       __restrict__ out) {
    int row = blockIdx.x;                 // 0 .. NB*NL-1
    int b = row >> 11, i = row & (NL - 1);
    int t = threadIdx.x;
    size_t base = ((size_t)b << 22) + ((size_t)i << 11);
    float4* orow = reinterpret_cast<float4*>(out + base);

    int len1 = __ldg(&len[2 * b]);
    if (i >= len1) {
        float4 z = make_float4(0.f, 0.f, 0.f, 0.f);
        stcs4(&orow[t], z);
        stcs4(&orow[256 + t], z);
        return;
    }
    int len2 = __ldg(&len[2 * b + 1]);
    const float4* prow = reinterpret_cast<const float4*>(sim + base);

    float4 vA = ldcs4(&prow[t]);
    float eA0 = ex2f(vA.x * SCALEV), eA1 = ex2f(vA.y * SCALEV);
    float eA2 = ex2f(vA.z * SCALEV), eA3 = ex2f(vA.w * SCALEV);

    int nvB = len2 - (1024 + 4 * t);
    float eB0 = 0.f, eB1 = 0.f, eB2 = 0.f, eB3 = 0.f;
    if (nvB > 0) {
        float4 vB = ldcs4(&prow[256 + t]);
        eB0 = ex2f(vB.x * SCALEV);
        if (nvB > 1) eB1 = ex2f(vB.y * SCALEV);
        if (nvB > 2) eB2 = ex2f(vB.z * SCALEV);
        if (nvB > 3) eB3 = ex2f(vB.w * SCALEV);
    }

    // --- block reduce row sum ---
    __shared__ float ssm[8];
    int lane = t & 31, wid = t >> 5;
    float s = (eA0 + eA1) + (eA2 + eA3) + (eB0 + eB1) + (eB2 + eB3);
#pragma unroll
    for (int o = 16; o; o >>= 1) s += __shfl_xor_sync(0xffffffffu, s, o);
    if (lane == 0) ssm[wid] = s;
    __syncthreads();
    float rs = (ssm[0] + ssm[1]) + (ssm[2] + ssm[3])
             + (ssm[4] + ssm[5]) + (ssm[6] + ssm[7]);
    float inv_rs = 1.0f / rs;

    const float4* gc = reinterpret_cast<const float4*>(g_ics + ((size_t)b << 11));

    // --- chunk A output (always fully valid) ---
    float4 icA = __ldg(&gc[t]);
    float4 oA;
    oA.x = sqrtap(fmaf(eA0 * eA0 * inv_rs, icA.x, EPSV));
    oA.y = sqrtap(fmaf(eA1 * eA1 * inv_rs, icA.y, EPSV));
    oA.z = sqrtap(fmaf(eA2 * eA2 * inv_rs, icA.z, EPSV));
    oA.w = sqrtap(fmaf(eA3 * eA3 * inv_rs, icA.w, EPSV));
    stcs4(&orow[t], oA);

    // --- chunk B output (masked -> exact zeros outside valid region) ---
    float4 oB = make_float4(0.f, 0.f, 0.f, 0.f);
    if (nvB > 0) {
        float4 icB = __ldg(&gc[256 + t]);
        oB.x = sqrtap(fmaf(eB0 * eB0 * inv_rs, icB.x, EPSV));
        if (nvB > 1) oB.y = sqrtap(fmaf(eB1 * eB1 * inv_rs, icB.y, EPSV));
        if (nvB > 2) oB.z = sqrtap(fmaf(eB2 * eB2 * inv_rs, icB.z, EPSV));
        if (nvB > 3) oB.w = sqrtap(fmaf(eB3 * eB3 * inv_rs, icB.w, EPSV));
    }
    stcs4(&orow[256 + t], oB);
}

// ---------------------------------------------------------------------------
extern "C" void kernel_launch(void* const* d_in, const int* in_sizes, int n_in,
                              void* d_out, int out_size) {
    const float* sim = (const float*)d_in[0];
    const int*   len = (const int*)d_in[1];
    if (n_in >= 2 && in_sizes[0] == 16) {   // defensive: swapped order
        sim = (const float*)d_in[1];
        len = (const int*)d_in[0];
    }
    float* out = (float*)d_out;

    dim3 g1(2, NSLAB, NB);                    // 2048 CTAs
    k_colstats<<<g1, 256>>>(sim, len);
    k_merge<<<(NB * NL) / 256, 256>>>();      // 64 CTAs
    k_out<<<NB * NL, 256>>>(sim, len, out);   // 16384 CTAs
}

// round 13
// speedup vs baseline: 1.0312x; 1.0312x over previous
#include <cuda_runtime.h>
#include <cstdint>

// BidirectionalSoftmax: B=8, L1=L2=2048, TAU=0.5, EPS=1e-8
// No-max softmax: e = exp2(sim*(1/TAU)*log2 e); out = sqrt(EPS + e*e*irs*ics)
//
//   k_colstats : 2048 CTAs (2 col-groups x 128 slabs x 8 b), slab = 16 rows,
//                unroll-8 float4. [equal-best measured 18.8us]
//   k_merge    : fold 128 slab partials -> 1/col_sum (plain loads).
//   k_out      : NEW: 2 rows per CTA (8192 CTAs). 4 front-batched LDG.128 per
//                thread (MLP 4), shared g_ics load across both rows, one
//                __syncthreads covering both row reductions, .cs hints.

#define NB    8
#define NL    2048
#define NSLAB 128
#define RPS   16                      /* rows per slab */
#define SCALEV 2.8853900817779268f    /* (1/0.5) * log2(e) */
#define EPSV  1e-8f

__device__ float g_cps[NB * NSLAB * NL];  // partial col sums of exp2(y)
__device__ float g_ics[NB * NL];          // 1/col_sum

__device__ __forceinline__ float ex2f(float x) {
    float r; asm("ex2.approx.f32 %0, %1;" : "=f"(r) : "f"(x)); return r;
}
__device__ __forceinline__ float sqrtap(float x) {
    float r; asm("sqrt.approx.f32 %0, %1;" : "=f"(r) : "f"(x)); return r;
}
__device__ __forceinline__ float4 ldcs4(const float4* p) {
    float4 v;
    asm volatile("ld.global.cs.v4.f32 {%0,%1,%2,%3}, [%4];"
                 : "=f"(v.x), "=f"(v.y), "=f"(v.z), "=f"(v.w) : "l"(p));
    return v;
}
__device__ __forceinline__ void stcs4(float4* p, float4 v) {
    asm volatile("st.global.cs.v4.f32 [%0], {%1,%2,%3,%4};"
                 :: "l"(p), "f"(v.x), "f"(v.y), "f"(v.z), "f"(v.w) : "memory");
}

// ---------------------------------------------------------------------------
// Pass 1: column sum partials. grid=(2, 128, 8) = 2048 CTAs, block=256.
// ---------------------------------------------------------------------------
__global__ void __launch_bounds__(256) k_colstats(const float* __restrict__ sim,
                                                  const int*   __restrict__ len) {
    int b = blockIdx.z, slab = blockIdx.y, grp = blockIdx.x;
    int t = threadIdx.x;
    int col = grp * 1024 + t * 4;
    int len1 = __ldg(&len[2 * b]);
    int len2 = __ldg(&len[2 * b + 1]);
    int r0 = slab * RPS;
    int rend = min(r0 + RPS, len1);

    float s0 = 0.f, s1 = 0.f, s2 = 0.f, s3 = 0.f;

    if (col < len2 && r0 < rend) {
        int nv = len2 - col;            // >= 1
        bool k1 = nv > 1, k2 = nv > 2, k3 = nv > 3;
        const float4* p = reinterpret_cast<const float4*>(sim)
                        + ((size_t)b << 20) + ((size_t)r0 << 9) + (col >> 2);
        int n = rend - r0;

#define PROC(v)                                        \
        do {                                           \
            s0 += ex2f((v).x * SCALEV);                \
            s1 += k1 ? ex2f((v).y * SCALEV) : 0.f;     \
            s2 += k2 ? ex2f((v).z * SCALEV) : 0.f;     \
            s3 += k3 ? ex2f((v).w * SCALEV) : 0.f;     \
        } while (0)

        int r = 0;
        for (; r + 8 <= n; r += 8) {
            float4 v[8];
#pragma unroll
            for (int u = 0; u < 8; u++) v[u] = p[u * 512];
            p += 8 * 512;
#pragma unroll
            for (int u = 0; u < 8; u++) PROC(v[u]);
        }
        for (; r < n; r++) { float4 v = p[0]; p += 512; PROC(v); }
#undef PROC
    }

    size_t idx = ((size_t)(b * NSLAB + slab) << 11) + col;
    *reinterpret_cast<float4*>(&g_cps[idx]) = make_float4(s0, s1, s2, s3);
}

// ---------------------------------------------------------------------------
// Pass 1b: fold 128 slab partials per (batch, column) -> 1/col_sum.
// ---------------------------------------------------------------------------
__global__ void __launch_bounds__(256) k_merge() {
    int idx = blockIdx.x * 256 + threadIdx.x;     // b*NL + j
    int b = idx >> 11, j = idx & (NL - 1);

    float acc = 0.f;
#pragma unroll 8
    for (int s = 0; s < NSLAB; s++)
        acc += g_cps[((size_t)(b * NSLAB + s) << 11) + j];
    g_ics[idx] = acc > 0.f ? (1.0f / acc) : 0.f;
}

// ---------------------------------------------------------------------------
// Pass 2: 2 rows per CTA. Thread t: cols [4t,4t+4) (A, always col-valid) and
// [1024+4t,..) (B, masked) for BOTH rows. 4 front-batched loads, one sync.
// ---------------------------------------------------------------------------
__global__ void __launch_bounds__(256) k_out(const float* __restrict__ sim,
                                             const int*   __restrict__ len,
                                             float*       __restrict__ out) {
    int cta = blockIdx.x;                 // 0 .. NB*NL/2-1
    int b = cta >> 10;
    int i0 = (cta & 1023) << 1;
    int t = threadIdx.x;
    size_t base = ((size_t)b << 22) + ((size_t)i0 << 11);
    float4* o0 = reinterpret_cast<float4*>(out + base);
    float4* o1 = o0 + 512;
    const float4 z = make_float4(0.f, 0.f, 0.f, 0.f);

    int len1 = __ldg(&len[2 * b]);
    if (i0 >= len1) {                     // i0 invalid => i0+1 invalid too
        stcs4(&o0[t], z); stcs4(&o0[256 + t], z);
        stcs4(&o1[t], z); stcs4(&o1[256 + t], z);
        return;
    }
    int len2 = __ldg(&len[2 * b + 1]);
    bool rv1 = (i0 + 1) < len1;

    int nvB = len2 - (1024 + 4 * t);
    bool wB = nvB > 0, m1 = nvB > 1, m2 = nvB > 2, m3 = nvB > 3;

    const float4* p0 = reinterpret_cast<const float4*>(sim + base);
    const float4* p1 = p0 + 512;

    // 4 front-batched loads (MLP 4)
    float4 vA0 = ldcs4(&p0[t]);
    float4 vA1 = rv1 ? ldcs4(&p1[t]) : z;
    float4 vB0 = wB ? ldcs4(&p0[256 + t]) : z;
    float4 vB1 = (rv1 && wB) ? ldcs4(&p1[256 + t]) : z;

    // row0 e's
    float a0 = ex2f(vA0.x * SCALEV), a1 = ex2f(vA0.y * SCALEV);
    float a2 = ex2f(vA0.z * SCALEV), a3 = ex2f(vA0.w * SCALEV);
    float c0 = wB ? ex2f(vB0.x * SCALEV) : 0.f;
    float c1 = m1 ? ex2f(vB0.y * SCALEV) : 0.f;
    float c2 = m2 ? ex2f(vB0.z * SCALEV) : 0.f;
    float c3 = m3 ? ex2f(vB0.w * SCALEV) : 0.f;
    float s0 = (a0 + a1) + (a2 + a3) + (c0 + c1) + (c2 + c3);

    // row1 e's (harmless garbage if !rv1; outputs guarded)
    float d0 = ex2f(vA1.x * SCALEV), d1 = ex2f(vA1.y * SCALEV);
    float d2 = ex2f(vA1.z * SCALEV), d3 = ex2f(vA1.w * SCALEV);
    float f0 = wB ? ex2f(vB1.x * SCALEV) : 0.f;
    float f1 = m1 ? ex2f(vB1.y * SCALEV) : 0.f;
    float f2 = m2 ? ex2f(vB1.z * SCALEV) : 0.f;
    float f3 = m3 ? ex2f(vB1.w * SCALEV) : 0.f;
    float s1 = (d0 + d1) + (d2 + d3) + (f0 + f1) + (f2 + f3);

    // block reduce both rows, one barrier
    __shared__ float ssm[16];
    int lane = t & 31, wid = t >> 5;
#pragma unroll
    for (int o = 16; o; o >>= 1) {
        s0 += __shfl_xor_sync(0xffffffffu, s0, o);
        s1 += __shfl_xor_sync(0xffffffffu, s1, o);
    }
    if (lane == 0) { ssm[wid] = s0; ssm[8 + wid] = s1; }
    __syncthreads();
    float rs0 = (ssm[0] + ssm[1]) + (ssm[2] + ssm[3])
              + (ssm[4] + ssm[5]) + (ssm[6] + ssm[7]);
    float rs1 = (ssm[8] + ssm[9]) + (ssm[10] + ssm[11])
              + (ssm[12] + ssm[13]) + (ssm[14] + ssm[15]);
    float inv0 = 1.0f / rs0;
    float inv1 = rv1 ? (1.0f / rs1) : 0.f;

    // shared column-reciprocal table load (once for both rows)
    const float4* gc = reinterpret_cast<const float4*>(g_ics + ((size_t)b << 11));
    float4 icA = __ldg(&gc[t]);
    float4 icB = wB ? __ldg(&gc[256 + t]) : z;

    // row0 outputs
    {
        float4 r;
        r.x = sqrtap(fmaf(a0 * a0 * inv0, icA.x, EPSV));
        r.y = sqrtap(fmaf(a1 * a1 * inv0, icA.y, EPSV));
        r.z = sqrtap(fmaf(a2 * a2 * inv0, icA.z, EPSV));
        r.w = sqrtap(fmaf(a3 * a3 * inv0, icA.w, EPSV));
        stcs4(&o0[t], r);
        float4 q = z;
        if (wB) {
            q.x = sqrtap(fmaf(c0 * c0 * inv0, icB.x, EPSV));
            if (m1) q.y = sqrtap(fmaf(c1 * c1 * inv0, icB.y, EPSV));
            if (m2) q.z = sqrtap(fmaf(c2 * c2 * inv0, icB.z, EPSV));
            if (m3) q.w = sqrtap(fmaf(c3 * c3 * inv0, icB.w, EPSV));
        }
        stcs4(&o0[256 + t], q);
    }
    // row1 outputs (guarded by rv1)
    {
        float4 r = z, q = z;
        if (rv1) {
            r.x = sqrtap(fmaf(d0 * d0 * inv1, icA.x, EPSV));
            r.y = sqrtap(fmaf(d1 * d1 * inv1, icA.y, EPSV));
            r.z = sqrtap(fmaf(d2 * d2 * inv1, icA.z, EPSV));
            r.w = sqrtap(fmaf(d3 * d3 * inv1, icA.w, EPSV));
            if (wB) {
                q.x = sqrtap(fmaf(f0 * f0 * inv1, icB.x, EPSV));
                if (m1) q.y = sqrtap(fmaf(f1 * f1 * inv1, icB.y, EPSV));
                if (m2) q.z = sqrtap(fmaf(f2 * f2 * inv1, icB.z, EPSV));
                if (m3) q.w = sqrtap(fmaf(f3 * f3 * inv1, icB.w, EPSV));
            }
        }
        stcs4(&o1[t], r);
        stcs4(&o1[256 + t], q);
    }
}

// ---------------------------------------------------------------------------
extern "C" void kernel_launch(void* const* d_in, const int* in_sizes, int n_in,
                              void* d_out, int out_size) {
    const float* sim = (const float*)d_in[0];
    const int*   len = (const int*)d_in[1];
    if (n_in >= 2 && in_sizes[0] == 16) {   // defensive: swapped order
        sim = (const float*)d_in[1];
        len = (const int*)d_in[0];
    }
    float* out = (float*)d_out;

    dim3 g1(2, NSLAB, NB);                      // 2048 CTAs
    k_colstats<<<g1, 256>>>(sim, len);
    k_merge<<<(NB * NL) / 256, 256>>>();        // 64 CTAs
    k_out<<<NB * NL / 2, 256>>>(sim, len, out); // 8192 CTAs
}